// round 2
// baseline (speedup 1.0000x reference)
#include <cuda_runtime.h>

// CBOW hierarchical softmax loss, fused single-block kernel.
// Inputs (metadata order):
//   d_in[0] context_idx  int32[10]
//   d_in[1] path_indices int32[17]
//   d_in[2] code_bits    int32[17]
//   d_in[3] ctx_emb      float32[100000*512]
//   d_in[4] node_emb     float32[200000*512]
// Output: float32[1] = loss

#define EMBED   512
#define WINDOW  10
#define PATHLEN 17
#define EPS     1e-9f

__global__ __launch_bounds__(EMBED, 1)
void cbow_hs_kernel(const int* __restrict__ ctx_idx,
                    const int* __restrict__ path_idx,
                    const int* __restrict__ code_bits,
                    const float* __restrict__ ctx_emb,
                    const float* __restrict__ node_emb,
                    float* __restrict__ out)
{
    __shared__ float h_s[EMBED];
    __shared__ float loss_s;

    const int tid  = threadIdx.x;
    const int wid  = tid >> 5;
    const int lane = tid & 31;

    if (tid == 0) loss_s = 0.0f;

    // ---- Phase A: front-load ALL gathers so node-row and ctx-row DRAM
    // latencies overlap (one exposed round-trip instead of two). ----

    // Warp wid owns path wid; warp 0 additionally owns path 16.
    const int npaths = (wid == 0) ? 2 : 1;
    int p0 = wid, p1 = 16;

    float4 nv[8];
    #pragma unroll
    for (int j = 0; j < 2; j++) {
        if (j < npaths) {
            const int p = (j == 0) ? p0 : p1;
            const long base = (long)__ldg(&path_idx[p]) * EMBED;
            const float4* row = (const float4*)(node_emb + base);
            #pragma unroll
            for (int i = 0; i < 4; i++)
                nv[j * 4 + i] = __ldg(&row[lane + 32 * i]);
        }
    }

    // h: thread `tid` owns dimension `tid`; 10 independent coalesced loads.
    float hv = 0.0f;
    #pragma unroll
    for (int w = 0; w < WINDOW; w++) {
        const long base = (long)__ldg(&ctx_idx[w]) * EMBED;
        hv += __ldg(&ctx_emb[base + tid]);
    }
    h_s[tid] = hv * (1.0f / WINDOW);
    __syncthreads();

    // ---- Phase B: dot products from registers x smem, warp reduce. ----
    const float4* h4 = (const float4*)h_s;
    #pragma unroll
    for (int j = 0; j < 2; j++) {
        if (j < npaths) {
            const int p = (j == 0) ? p0 : p1;
            float dot = 0.0f;
            #pragma unroll
            for (int i = 0; i < 4; i++) {
                const float4 hh = h4[lane + 32 * i];
                const float4 n  = nv[j * 4 + i];
                dot += n.x * hh.x + n.y * hh.y + n.z * hh.z + n.w * hh.w;
            }
            #pragma unroll
            for (int off = 16; off; off >>= 1)
                dot += __shfl_xor_sync(0xffffffffu, dot, off);
            if (lane == 0) {
                const float s = 1.0f / (1.0f + expf(-dot));
                const int bit = __ldg(&code_bits[p]);
                const float prob = (bit == 1) ? s : (1.0f - s);
                atomicAdd(&loss_s, -logf(prob + EPS));
            }
        }
    }
    __syncthreads();
    if (tid == 0) out[0] = loss_s;
}

extern "C" void kernel_launch(void* const* d_in, const int* in_sizes, int n_in,
                              void* d_out, int out_size)
{
    const int*   ctx_idx   = (const int*)d_in[0];
    const int*   path_idx  = (const int*)d_in[1];
    const int*   code_bits = (const int*)d_in[2];
    const float* ctx_emb   = (const float*)d_in[3];
    const float* node_emb  = (const float*)d_in[4];
    float*       out       = (float*)d_out;

    cbow_hs_kernel<<<1, EMBED>>>(ctx_idx, path_idx, code_bits,
                                 ctx_emb, node_emb, out);
}